// round 15
// baseline (speedup 1.0000x reference)
#include <cuda_runtime.h>
#include <math.h>

#define EPSF    1e-8f
#define LAMBDAF 1e-3f
#define LOG2E   1.442695041f
#define NTH 128
#define NW  4
#define BPW 72    // 288 / 4 warps

// smem floats: xr 4608 | fac 288 | p1 2048 | p2 2048 | prs 128 | mu 512 | A 512 | B 512 | lna 32 | aout 32
#define SMEM_FLOATS (4608 + 288 + 2048 + 2048 + 128 + 512 + 512 + 512 + 32 + 32)

typedef unsigned long long u64t;

// transposed weights: W2[B][j][c] as 16-byte chunks, index = B*128 + j*32 + c
__device__ uint4 g_w2[288 * 128];

__device__ __forceinline__ u64t pack2(float a, float b) {
    u64t r; asm("mov.b64 %0,{%1,%2};" : "=l"(r) : "f"(a), "f"(b)); return r;
}
__device__ __forceinline__ u64t dup2(float a) { return pack2(a, a); }
__device__ __forceinline__ void unpack2(u64t v, float& a, float& b) {
    asm("mov.b64 {%0,%1},%2;" : "=f"(a), "=f"(b) : "l"(v));
}
__device__ __forceinline__ u64t fma2(u64t a, u64t b, u64t c) {
    u64t d; asm("fma.rn.f32x2 %0,%1,%2,%3;" : "=l"(d) : "l"(a), "l"(b), "l"(c)); return d;
}
__device__ __forceinline__ u64t mul2(u64t a, u64t b) {
    u64t d; asm("mul.rn.f32x2 %0,%1,%2;" : "=l"(d) : "l"(a), "l"(b)); return d;
}
__device__ __forceinline__ u64t add2(u64t a, u64t b) {
    u64t d; asm("add.rn.f32x2 %0,%1,%2;" : "=l"(d) : "l"(a), "l"(b)); return d;
}
__device__ __forceinline__ float ex2f(float x) {
    float r; asm("ex2.approx.ftz.f32 %0, %1;" : "=f"(r) : "f"(x)); return r;
}

// warp max of f32: LOP3-friendly monotonic u32 key + redux.sync.max.u32
__device__ __forceinline__ float warp_max_f32(float v) {
    unsigned int b   = __float_as_uint(v);
    unsigned int sb  = (unsigned int)((int)b >> 31);
    unsigned int key = b ^ (sb | 0x80000000u);
    unsigned int m;
    asm("redux.sync.max.u32 %0, %1, 0xffffffff;" : "=r"(m) : "r"(key));
    unsigned int sm_ = (unsigned int)((int)m >> 31);
    unsigned int mb  = m ^ (~sm_ | 0x80000000u);
    return __uint_as_float(mb);
}

__device__ __forceinline__ unsigned int warp_add_u32(unsigned int v) {
    unsigned int s;
    asm("redux.sync.add.u32 %0, %1, 0xffffffff;" : "=r"(s) : "r"(v));
    return s;
}

// one-time (per launch) W transpose: out[B*128 + j*32 + c] = in[(B*32+c)*4 + j]
__global__ void transpose_w_kernel(const uint4* __restrict__ win) {
    int idx = blockIdx.x * blockDim.x + threadIdx.x;
    if (idx >= 288 * 128) return;
    int B   = idx >> 7;
    int rem = idx & 127;
    int j   = rem >> 5;
    int c   = rem & 31;
    g_w2[idx] = win[(size_t)(B * 32 + c) * 4 + j];
}

// ===================== one EM sweep (compile-time specialized, deferred moments) ==========
template<int S>
__device__ __forceinline__ void do_sweep(
    const float* __restrict__ s_xr, const float* __restrict__ s_fac,
    float* __restrict__ s_p1, float* __restrict__ s_p2, float* __restrict__ s_prs,
    float* __restrict__ orp0,
    const ulonglong2* __restrict__ wp0,
    const u64t* A2, const u64t* B2, float lnac, int w, int c)
{
    u64t acc1[8], acc2[8];
    #pragma unroll
    for (int h = 0; h < 8; ++h) { acc1[h] = 0ull; acc2[h] = 0ull; }
    float prs = 0.f;

    const ulonglong2* wp   = wp0;
    const float*      facp = s_fac + w * BPW;
    const float4*     xp4  = reinterpret_cast<const float4*>(s_xr + (w * BPW) * 16);
    float*            orp  = orp0;

    ulonglong2 a0 = wp[0], a1 = wp[32], a2 = wp[64], a3 = wp[96];

    u64t vp_prev[8];
    float r2_prev = 0.f;
    if (S > 0) {
        #pragma unroll
        for (int h = 0; h < 8; ++h) vp_prev[h] = 0ull;
    }

    // LAST = true for the final iteration (no W reload)
    auto body = [&](int bi, bool last) {
        // ---- v compute (consumes a0..a3) ----
        u64t vp[8];
        #pragma unroll
        for (int i = 0; i < 4; ++i) {
            float4 xi = xp4[i];
            u64t x0 = dup2(xi.x), x1 = dup2(xi.y), x2 = dup2(xi.z), x3 = dup2(xi.w);
            u64t lo = mul2(x0, a0.x);
            lo = fma2(x1, a1.x, lo);
            lo = fma2(x2, a2.x, lo);
            lo = fma2(x3, a3.x, lo);
            u64t hi = mul2(x0, a0.y);
            hi = fma2(x1, a1.y, hi);
            hi = fma2(x2, a2.y, hi);
            hi = fma2(x3, a3.y, hi);
            vp[2*i]   = lo;   // p = 4i+0, 4i+1
            vp[2*i+1] = hi;   // p = 4i+2, 4i+3
        }
        xp4 += 4;

        // ---- W regs now dead: reload next tile in place (L2 latency covered by tail) ----
        if (!last) {
            wp += 128;
            a0 = wp[0]; a1 = wp[32]; a2 = wp[64]; a3 = wp[96];
        }

        if (S == 0) {
            float r2 = facp[bi] * (1.0f / 32.0f);
            prs += r2;
            u64t rp = dup2(r2);
            #pragma unroll
            for (int h = 0; h < 8; ++h) {
                u64t t = mul2(rp, vp[h]);
                acc1[h] = add2(acc1[h], t);
                acc2[h] = fma2(t, vp[h], acc2[h]);
            }
        } else {
            // ---- score (log2 units): lnac + Σ_p (A v^2 + B v), 2 chains ----
            u64t sa = 0ull, sb = 0ull;
            #pragma unroll
            for (int h = 0; h < 4; ++h) {
                u64t t0 = fma2(vp[2*h],   A2[2*h],   B2[2*h]);
                u64t t1 = fma2(vp[2*h+1], A2[2*h+1], B2[2*h+1]);
                sa = fma2(vp[2*h],   t0, sa);
                sb = fma2(vp[2*h+1], t1, sb);
            }
            float sl, sh;
            unpack2(add2(sa, sb), sl, sh);
            float sc = lnac + sl + sh;
            float m  = warp_max_f32(sc);
            float e  = ex2f(sc - m + 26.f);
            unsigned int q  = __float2uint_rn(e);
            unsigned int du = warp_add_u32(q);

            // ---- deferred moments of previous bi (independent of this REDUX) ----
            {
                u64t rp = dup2(r2_prev);
                #pragma unroll
                for (int h = 0; h < 8; ++h) {
                    u64t t = mul2(rp, vp_prev[h]);
                    acc1[h] = add2(acc1[h], t);
                    acc2[h] = fma2(t, vp_prev[h], acc2[h]);
                }
                prs += r2_prev;
            }

            float r = __fdividef(e, __uint2float_rn(du));
            if (S == 2) { *orp = r; orp += 32; }

            #pragma unroll
            for (int h = 0; h < 8; ++h) vp_prev[h] = vp[h];
            r2_prev = r * facp[bi];
        }
    };

    #pragma unroll 2
    for (int bi = 0; bi < BPW - 1; ++bi) body(bi, false);
    body(BPW - 1, true);

    if (S > 0) {
        // final deferred moments
        u64t rp = dup2(r2_prev);
        #pragma unroll
        for (int h = 0; h < 8; ++h) {
            u64t t = mul2(rp, vp_prev[h]);
            acc1[h] = add2(acc1[h], t);
            acc2[h] = fma2(t, vp_prev[h], acc2[h]);
        }
        prs += r2_prev;
    }

    // store per-warp partials
    ulonglong2* p1v = reinterpret_cast<ulonglong2*>(s_p1 + w * 512 + c * 16);
    ulonglong2* p2v = reinterpret_cast<ulonglong2*>(s_p2 + w * 512 + c * 16);
    #pragma unroll
    for (int i = 0; i < 4; ++i) {
        p1v[i] = make_ulonglong2(acc1[2*i], acc1[2*i+1]);
        p2v[i] = make_ulonglong2(acc2[2*i], acc2[2*i+1]);
    }
    s_prs[w * 32 + c] = prs;
}

// ===================== reduce partials -> stats =====================
__device__ __forceinline__ void reduce_phase(
    const float* __restrict__ s_p1, const float* __restrict__ s_p2,
    const float* __restrict__ s_prs,
    float* __restrict__ s_mu, float* __restrict__ s_A, float* __restrict__ s_B,
    float* __restrict__ s_lna, float* __restrict__ s_aout,
    const float* __restrict__ beta_u, const float* __restrict__ beta_a, int tid)
{
    #pragma unroll
    for (int k = 0; k < 4; ++k) {
        int cp = tid + k * 128;       // cp = c2*16 + p
        int c2 = cp >> 4, p = cp & 15;
        float e1 = 0.f, e2 = 0.f, rs = 0.f;
        #pragma unroll
        for (int ww = 0; ww < NW; ++ww) {
            e1 += s_p1[ww * 512 + cp];
            e2 += s_p2[ww * 512 + cp];
            rs += s_prs[ww * 32 + c2];
        }
        float invr = 1.0f / (rs + EPSF);
        float S    = rs * invr;
        float mu   = e1 * invr;
        float E2   = e2 * invr;
        float var  = E2 - mu * mu * (2.0f - S);
        float sig  = fmaxf(var, 0.f) + EPSF;
        float hls  = 0.5f * __logf(sig);           // natural log (cost term)
        float I    = (0.5f * LOG2E) / sig;         // log2-domain precision
        int pidx   = 2 * ((p >> 1) * 32 + c2) + (p & 1);
        s_mu[p * 32 + c2] = mu;
        s_A [pidx] = -I;
        s_B [pidx] = 2.0f * mu * I;
        float im2  = mu * mu * I;                  // fold into softmax const
        float hsum = hls, isum = im2;
        #pragma unroll
        for (int o = 8; o; o >>= 1) {
            hsum += __shfl_xor_sync(0xffffffffu, hsum, o, 16);
            isum += __shfl_xor_sync(0xffffffffu, isum, o, 16);
        }
        if (p == 0) {
            float cost = rs * (16.f * beta_u[c2] + hsum);
            float av   = 1.0f / (1.0f + __expf(-LAMBDAF * (beta_a[c2] - cost)));
            s_aout[c2] = av;
            s_lna [c2] = (__logf(av) - hsum) * LOG2E - isum;
        }
    }
}

__global__ void __launch_bounds__(NTH, 4)
emcaps_kernel(const float* __restrict__ x,
              const float* __restrict__ beta_u,
              const float* __restrict__ beta_a,
              float* __restrict__ out_main,
              float* __restrict__ out_r)
{
    extern __shared__ float sm[];
    float* s_xr   = sm;               // [9*512]  patch matrices
    float* s_fac  = s_xr  + 4608;     // [288]    a_in/(a_in+eps)
    float* s_p1   = s_fac + 288;      // [4*512]  per-warp partials Σ r2*v
    float* s_p2   = s_p1  + 2048;     // [4*512]  per-warp partials Σ r2*v^2
    float* s_prs  = s_p2  + 2048;     // [4*32]   per-warp partials Σ r2
    float* s_mu   = s_prs + 128;      // [512] layout [p][c] (for final output)
    float* s_A    = s_mu  + 512;      // [512] paired u64[h*32+c] = (A[2h], A[2h+1]), A = -I
    float* s_B    = s_A   + 512;      // [512] paired, B = 2*mu*I
    float* s_lna  = s_B   + 512;      // [32]  per-c softmax const
    float* s_aout = s_lna + 32;       // [32]

    const int n   = blockIdx.x;       // 508
    const int tid = threadIdx.x;
    const int w   = tid >> 5;         // 0..3
    const int c   = tid & 31;

    // ---- load the 9 patch rows: g = 9n+q -> x[b, k1+j, 0, :] ----
    for (int idx = tid; idx < 9 * 544; idx += NTH) {
        int q  = idx / 544;
        int rr = idx - q * 544;
        int g  = n * 9 + q;
        int b  = g / 2286;
        int k1 = (g - b * 2286) / 762;
        int j  = g % 254;
        const float* row = x + (size_t)((b * 256 + (k1 + j)) * 4) * 544;  // h = 0
        float val = row[rr];
        if (rr < 512) s_xr[q * 512 + rr] = val;
        else          s_fac[q * 32 + rr - 512] = val / (val + EPSF);
    }
    __syncthreads();

    u64t A2[8], B2[8];
    float lnac = 0.f;
    #pragma unroll
    for (int h = 0; h < 8; ++h) { A2[h] = 0ull; B2[h] = 0ull; }

    const ulonglong2* w2  = reinterpret_cast<const ulonglong2*>(g_w2);
    const ulonglong2* wp0 = w2 + (size_t)(w * BPW) * 128 + c;
    float* orp0 = out_r + (size_t)n * 9216 + (size_t)(w * BPW) * 32 + c;

    // ---- sweep 0 ----
    do_sweep<0>(s_xr, s_fac, s_p1, s_p2, s_prs, orp0, wp0, A2, B2, lnac, w, c);
    __syncthreads();
    reduce_phase(s_p1, s_p2, s_prs, s_mu, s_A, s_B, s_lna, s_aout, beta_u, beta_a, tid);
    __syncthreads();
    {
        lnac = s_lna[c];
        const u64t* Ap = reinterpret_cast<const u64t*>(s_A) + c;
        const u64t* Bp = reinterpret_cast<const u64t*>(s_B) + c;
        #pragma unroll
        for (int h = 0; h < 8; ++h) { A2[h] = Ap[h * 32]; B2[h] = Bp[h * 32]; }
    }

    // ---- sweep 1 ----
    do_sweep<1>(s_xr, s_fac, s_p1, s_p2, s_prs, orp0, wp0, A2, B2, lnac, w, c);
    __syncthreads();
    reduce_phase(s_p1, s_p2, s_prs, s_mu, s_A, s_B, s_lna, s_aout, beta_u, beta_a, tid);
    __syncthreads();
    {
        lnac = s_lna[c];
        const u64t* Ap = reinterpret_cast<const u64t*>(s_A) + c;
        const u64t* Bp = reinterpret_cast<const u64t*>(s_B) + c;
        #pragma unroll
        for (int h = 0; h < 8; ++h) { A2[h] = Ap[h * 32]; B2[h] = Bp[h * 32]; }
    }

    // ---- sweep 2 (writes out_r) ----
    do_sweep<2>(s_xr, s_fac, s_p1, s_p2, s_prs, orp0, wp0, A2, B2, lnac, w, c);
    __syncthreads();
    reduce_phase(s_p1, s_p2, s_prs, s_mu, s_A, s_B, s_lna, s_aout, beta_u, beta_a, tid);
    __syncthreads();

    // ---- final outputs ----
    #pragma unroll
    for (int k = 0; k < 4; ++k) {
        int i = tid + k * 128;
        out_main[(size_t)n * 544 + i] = s_mu[(i & 15) * 32 + (i >> 4)];
    }
    if (tid < 32) out_main[(size_t)n * 544 + 512 + tid] = s_aout[tid];
}

extern "C" void kernel_launch(void* const* d_in, const int* in_sizes, int n_in,
                              void* d_out, int out_size) {
    const float* x  = (const float*)d_in[0];
    const float* Wt = (const float*)d_in[1];
    const float* bu = (const float*)d_in[2];
    const float* ba = (const float*)d_in[3];
    float* out  = (float*)d_out;
    float* outr = out + (size_t)2 * 254 * 544;

    transpose_w_kernel<<<(288 * 128 + 255) / 256, 256>>>((const uint4*)Wt);

    const int smem_bytes = SMEM_FLOATS * 4;
    cudaFuncSetAttribute(emcaps_kernel, cudaFuncAttributeMaxDynamicSharedMemorySize, smem_bytes);
    emcaps_kernel<<<508, NTH, smem_bytes>>>(x, bu, ba, out, outr);
}

// round 16
// speedup vs baseline: 1.0140x; 1.0140x over previous
#include <cuda_runtime.h>
#include <math.h>

#define EPSF    1e-8f
#define LAMBDAF 1e-3f
#define LOG2E   1.442695041f
#define NTH 128
#define NW  4
#define BPW 72    // 288 / 4 warps

// smem floats: xr 4608 | fac 288 | p1 2048 | p2 2048 | prs 128 | mu 512 | A 512 | B 512 | lna 32 | aout 32
#define SMEM_FLOATS (4608 + 288 + 2048 + 2048 + 128 + 512 + 512 + 512 + 32 + 32)

typedef unsigned long long u64t;

// transposed weights: W2[B][j][c] as 16-byte chunks, index = B*128 + j*32 + c
__device__ uint4 g_w2[288 * 128];

__device__ __forceinline__ u64t pack2(float a, float b) {
    u64t r; asm("mov.b64 %0,{%1,%2};" : "=l"(r) : "f"(a), "f"(b)); return r;
}
__device__ __forceinline__ u64t dup2(float a) { return pack2(a, a); }
__device__ __forceinline__ void unpack2(u64t v, float& a, float& b) {
    asm("mov.b64 {%0,%1},%2;" : "=f"(a), "=f"(b) : "l"(v));
}
__device__ __forceinline__ u64t fma2(u64t a, u64t b, u64t c) {
    u64t d; asm("fma.rn.f32x2 %0,%1,%2,%3;" : "=l"(d) : "l"(a), "l"(b), "l"(c)); return d;
}
__device__ __forceinline__ u64t mul2(u64t a, u64t b) {
    u64t d; asm("mul.rn.f32x2 %0,%1,%2;" : "=l"(d) : "l"(a), "l"(b)); return d;
}
__device__ __forceinline__ u64t add2(u64t a, u64t b) {
    u64t d; asm("add.rn.f32x2 %0,%1,%2;" : "=l"(d) : "l"(a), "l"(b)); return d;
}
__device__ __forceinline__ float ex2f(float x) {
    float r; asm("ex2.approx.ftz.f32 %0, %1;" : "=f"(r) : "f"(x)); return r;
}

// warp max of f32: LOP3-friendly monotonic u32 key + redux.sync.max.u32
__device__ __forceinline__ float warp_max_f32(float v) {
    unsigned int b   = __float_as_uint(v);
    unsigned int sb  = (unsigned int)((int)b >> 31);
    unsigned int key = b ^ (sb | 0x80000000u);
    unsigned int m;
    asm("redux.sync.max.u32 %0, %1, 0xffffffff;" : "=r"(m) : "r"(key));
    unsigned int sm_ = (unsigned int)((int)m >> 31);
    unsigned int mb  = m ^ (~sm_ | 0x80000000u);
    return __uint_as_float(mb);
}

__device__ __forceinline__ unsigned int warp_add_u32(unsigned int v) {
    unsigned int s;
    asm("redux.sync.add.u32 %0, %1, 0xffffffff;" : "=r"(s) : "r"(v));
    return s;
}

// one-time (per launch) W transpose: out[B*128 + j*32 + c] = in[(B*32+c)*4 + j]
__global__ void transpose_w_kernel(const uint4* __restrict__ win) {
    int idx = blockIdx.x * blockDim.x + threadIdx.x;
    if (idx >= 288 * 128) return;
    int B   = idx >> 7;
    int rem = idx & 127;
    int j   = rem >> 5;
    int c   = rem & 31;
    g_w2[idx] = win[(size_t)(B * 32 + c) * 4 + j];
}

// ===================== one EM sweep (compile-time specialized) =====================
template<int S>
__device__ __forceinline__ void do_sweep(
    const float* __restrict__ s_xr, const float* __restrict__ s_fac,
    float* __restrict__ s_p1, float* __restrict__ s_p2, float* __restrict__ s_prs,
    float* __restrict__ orp0,
    const ulonglong2* __restrict__ wp0,
    const u64t* A2, const u64t* B2, float lnac, int w, int c)
{
    u64t acc1[8], acc2[8];
    #pragma unroll
    for (int h = 0; h < 8; ++h) { acc1[h] = 0ull; acc2[h] = 0ull; }
    float prs = 0.f;

    const ulonglong2* wp = wp0;
    ulonglong2 a0 = wp[0], a1 = wp[32], a2 = wp[64], a3 = wp[96];
    float* orp = orp0;

    auto body = [&](int Bq, ulonglong2 c0, ulonglong2 c1, ulonglong2 c2, ulonglong2 c3) {
        const float4* xp4 = reinterpret_cast<const float4*>(s_xr + Bq * 16);
        u64t vp[8];
        #pragma unroll
        for (int i = 0; i < 4; ++i) {
            float4 xi = xp4[i];
            u64t x0 = dup2(xi.x), x1 = dup2(xi.y), x2 = dup2(xi.z), x3 = dup2(xi.w);
            u64t lo = mul2(x0, c0.x);
            lo = fma2(x1, c1.x, lo);
            lo = fma2(x2, c2.x, lo);
            lo = fma2(x3, c3.x, lo);
            u64t hi = mul2(x0, c0.y);
            hi = fma2(x1, c1.y, hi);
            hi = fma2(x2, c2.y, hi);
            hi = fma2(x3, c3.y, hi);
            vp[2*i]   = lo;   // p = 4i+0, 4i+1
            vp[2*i+1] = hi;   // p = 4i+2, 4i+3
        }

        float r2;
        if (S == 0) {
            r2 = s_fac[Bq] * (1.0f / 32.0f);
        } else {
            // score = lnac + Σ_p (A*v^2 + B*v)   (log2 units), 2 chains
            u64t sa = 0ull, sb = 0ull;
            #pragma unroll
            for (int h = 0; h < 4; ++h) {
                u64t t0 = fma2(vp[2*h],   A2[2*h],   B2[2*h]);
                u64t t1 = fma2(vp[2*h+1], A2[2*h+1], B2[2*h+1]);
                sa = fma2(vp[2*h],   t0, sa);
                sb = fma2(vp[2*h+1], t1, sb);
            }
            float sl, sh;
            unpack2(add2(sa, sb), sl, sh);
            float sc = lnac + sl + sh;
            float m  = warp_max_f32(sc);
            unsigned int q  = __float2uint_rn(ex2f(sc - m + 26.f));
            unsigned int du = warp_add_u32(q);
            float r  = __fdividef(__uint2float_rn(q), __uint2float_rn(du));
            if (S == 2) { *orp = r; orp += 32; }
            r2 = r * s_fac[Bq];
        }

        prs += r2;
        u64t r2p = dup2(r2);
        #pragma unroll
        for (int h = 0; h < 8; ++h) {
            u64t t = mul2(r2p, vp[h]);
            acc1[h] = add2(acc1[h], t);
            acc2[h] = fma2(t, vp[h], acc2[h]);
        }
    };

    // peeled loop: unconditional prefetch for bi < BPW-1
    #pragma unroll 2
    for (int bi = 0; bi < BPW - 1; ++bi) {
        ulonglong2 b0 = wp[128], b1 = wp[160], b2 = wp[192], b3 = wp[224];
        body(w * BPW + bi, a0, a1, a2, a3);
        a0 = b0; a1 = b1; a2 = b2; a3 = b3;
        wp += 128;
    }
    body(w * BPW + BPW - 1, a0, a1, a2, a3);

    // store per-warp partials
    ulonglong2* p1v = reinterpret_cast<ulonglong2*>(s_p1 + w * 512 + c * 16);
    ulonglong2* p2v = reinterpret_cast<ulonglong2*>(s_p2 + w * 512 + c * 16);
    #pragma unroll
    for (int i = 0; i < 4; ++i) {
        p1v[i] = make_ulonglong2(acc1[2*i], acc1[2*i+1]);
        p2v[i] = make_ulonglong2(acc2[2*i], acc2[2*i+1]);
    }
    s_prs[w * 32 + c] = prs;
}

// ===================== reduce partials -> stats =====================
__device__ __forceinline__ void reduce_phase(
    const float* __restrict__ s_p1, const float* __restrict__ s_p2,
    const float* __restrict__ s_prs,
    float* __restrict__ s_mu, float* __restrict__ s_A, float* __restrict__ s_B,
    float* __restrict__ s_lna, float* __restrict__ s_aout,
    const float* __restrict__ beta_u, const float* __restrict__ beta_a, int tid)
{
    #pragma unroll
    for (int k = 0; k < 4; ++k) {
        int cp = tid + k * 128;       // cp = c2*16 + p
        int c2 = cp >> 4, p = cp & 15;
        float e1 = 0.f, e2 = 0.f, rs = 0.f;
        #pragma unroll
        for (int ww = 0; ww < NW; ++ww) {
            e1 += s_p1[ww * 512 + cp];
            e2 += s_p2[ww * 512 + cp];
            rs += s_prs[ww * 32 + c2];
        }
        float invr = 1.0f / (rs + EPSF);
        float S    = rs * invr;
        float mu   = e1 * invr;
        float E2   = e2 * invr;
        float var  = E2 - mu * mu * (2.0f - S);
        float sig  = fmaxf(var, 0.f) + EPSF;
        float hls  = 0.5f * __logf(sig);           // natural log (cost term)
        float I    = (0.5f * LOG2E) / sig;         // log2-domain precision
        int pidx   = 2 * ((p >> 1) * 32 + c2) + (p & 1);
        s_mu[p * 32 + c2] = mu;
        s_A [pidx] = -I;
        s_B [pidx] = 2.0f * mu * I;
        float im2  = mu * mu * I;                  // fold into softmax const
        float hsum = hls, isum = im2;
        #pragma unroll
        for (int o = 8; o; o >>= 1) {
            hsum += __shfl_xor_sync(0xffffffffu, hsum, o, 16);
            isum += __shfl_xor_sync(0xffffffffu, isum, o, 16);
        }
        if (p == 0) {
            float cost = rs * (16.f * beta_u[c2] + hsum);
            float av   = 1.0f / (1.0f + __expf(-LAMBDAF * (beta_a[c2] - cost)));
            s_aout[c2] = av;
            s_lna [c2] = (__logf(av) - hsum) * LOG2E - isum;
        }
    }
}

__global__ void __launch_bounds__(NTH, 4)
emcaps_kernel(const float* __restrict__ x,
              const float* __restrict__ beta_u,
              const float* __restrict__ beta_a,
              float* __restrict__ out_main,
              float* __restrict__ out_r)
{
    extern __shared__ float sm[];
    float* s_xr   = sm;               // [9*512]  patch matrices
    float* s_fac  = s_xr  + 4608;     // [288]    a_in/(a_in+eps)
    float* s_p1   = s_fac + 288;      // [4*512]  per-warp partials Σ r2*v
    float* s_p2   = s_p1  + 2048;     // [4*512]  per-warp partials Σ r2*v^2
    float* s_prs  = s_p2  + 2048;     // [4*32]   per-warp partials Σ r2
    float* s_mu   = s_prs + 128;      // [512] layout [p][c] (for final output)
    float* s_A    = s_mu  + 512;      // [512] paired u64[h*32+c] = (A[2h], A[2h+1]), A = -I
    float* s_B    = s_A   + 512;      // [512] paired, B = 2*mu*I
    float* s_lna  = s_B   + 512;      // [32]  per-c softmax const
    float* s_aout = s_lna + 32;       // [32]

    const int n   = blockIdx.x;       // 508
    const int tid = threadIdx.x;
    const int w   = tid >> 5;         // 0..3
    const int c   = tid & 31;

    // ---- convoy breaker: stagger co-resident CTAs by ~300 cyc steps ----
    // Co-scheduled CTAs run identical code in lockstep and stall at the same
    // REDUX/MUFU windows; a one-time phase offset lets them fill each other's
    // pipeline bubbles. Deterministic w.r.t. output.
    {
        unsigned int target = (blockIdx.x & 3u) * 300u;
        if (target) {
            unsigned long long t0 = clock64();
            while ((unsigned long long)(clock64() - t0) < target) { }
        }
    }

    // ---- load the 9 patch rows: g = 9n+q -> x[b, k1+j, 0, :] ----
    for (int idx = tid; idx < 9 * 544; idx += NTH) {
        int q  = idx / 544;
        int rr = idx - q * 544;
        int g  = n * 9 + q;
        int b  = g / 2286;
        int k1 = (g - b * 2286) / 762;
        int j  = g % 254;
        const float* row = x + (size_t)((b * 256 + (k1 + j)) * 4) * 544;  // h = 0
        float val = row[rr];
        if (rr < 512) s_xr[q * 512 + rr] = val;
        else          s_fac[q * 32 + rr - 512] = val / (val + EPSF);
    }
    __syncthreads();

    u64t A2[8], B2[8];
    float lnac = 0.f;
    #pragma unroll
    for (int h = 0; h < 8; ++h) { A2[h] = 0ull; B2[h] = 0ull; }

    const ulonglong2* w2  = reinterpret_cast<const ulonglong2*>(g_w2);
    const ulonglong2* wp0 = w2 + (size_t)(w * BPW) * 128 + c;
    float* orp0 = out_r + (size_t)n * 9216 + (size_t)(w * BPW) * 32 + c;

    // ---- sweep 0 ----
    do_sweep<0>(s_xr, s_fac, s_p1, s_p2, s_prs, orp0, wp0, A2, B2, lnac, w, c);
    __syncthreads();
    reduce_phase(s_p1, s_p2, s_prs, s_mu, s_A, s_B, s_lna, s_aout, beta_u, beta_a, tid);
    __syncthreads();
    {
        lnac = s_lna[c];
        const u64t* Ap = reinterpret_cast<const u64t*>(s_A) + c;
        const u64t* Bp = reinterpret_cast<const u64t*>(s_B) + c;
        #pragma unroll
        for (int h = 0; h < 8; ++h) { A2[h] = Ap[h * 32]; B2[h] = Bp[h * 32]; }
    }

    // ---- sweep 1 ----
    do_sweep<1>(s_xr, s_fac, s_p1, s_p2, s_prs, orp0, wp0, A2, B2, lnac, w, c);
    __syncthreads();
    reduce_phase(s_p1, s_p2, s_prs, s_mu, s_A, s_B, s_lna, s_aout, beta_u, beta_a, tid);
    __syncthreads();
    {
        lnac = s_lna[c];
        const u64t* Ap = reinterpret_cast<const u64t*>(s_A) + c;
        const u64t* Bp = reinterpret_cast<const u64t*>(s_B) + c;
        #pragma unroll
        for (int h = 0; h < 8; ++h) { A2[h] = Ap[h * 32]; B2[h] = Bp[h * 32]; }
    }

    // ---- sweep 2 (writes out_r) ----
    do_sweep<2>(s_xr, s_fac, s_p1, s_p2, s_prs, orp0, wp0, A2, B2, lnac, w, c);
    __syncthreads();
    reduce_phase(s_p1, s_p2, s_prs, s_mu, s_A, s_B, s_lna, s_aout, beta_u, beta_a, tid);
    __syncthreads();

    // ---- final outputs ----
    #pragma unroll
    for (int k = 0; k < 4; ++k) {
        int i = tid + k * 128;
        out_main[(size_t)n * 544 + i] = s_mu[(i & 15) * 32 + (i >> 4)];
    }
    if (tid < 32) out_main[(size_t)n * 544 + 512 + tid] = s_aout[tid];
}

extern "C" void kernel_launch(void* const* d_in, const int* in_sizes, int n_in,
                              void* d_out, int out_size) {
    const float* x  = (const float*)d_in[0];
    const float* Wt = (const float*)d_in[1];
    const float* bu = (const float*)d_in[2];
    const float* ba = (const float*)d_in[3];
    float* out  = (float*)d_out;
    float* outr = out + (size_t)2 * 254 * 544;

    transpose_w_kernel<<<(288 * 128 + 255) / 256, 256>>>((const uint4*)Wt);

    const int smem_bytes = SMEM_FLOATS * 4;
    cudaFuncSetAttribute(emcaps_kernel, cudaFuncAttributeMaxDynamicSharedMemorySize, smem_bytes);
    emcaps_kernel<<<508, NTH, smem_bytes>>>(x, bu, ba, out, outr);
}